// round 4
// baseline (speedup 1.0000x reference)
#include <cuda_runtime.h>
#include <cstdint>

#define B_  2
#define C_  256
#define KCOL 2304   // C_ * 9

// ---------------- scratch (device globals: allocation-free) ----------------
__device__ float g_corr[2 * 289 * 64 * 64];   // max level-0 correlation
__device__ float g_off [2 *  72 * 64 * 64];   // offsets
__device__ float g_col [2 * KCOL * 64 * 64];  // im2col buffer (~76 MB)

// ---------------- 1. windowed pointwise correlation ----------------
// corr[b,k,h,w] = (1/C) * sum_c x1[b,c,h,w] * x0[b,c,h+oy,w+ox], zero OOB.
// block = 32 pixels x 8 shifts: f1 lines reused by all 8 warps via L1.
__global__ void corr_kernel(const float* __restrict__ x,
                            int H, int W, int disp, int stride, int K2)
{
    const int HW  = H * W;
    const int CHW = C_ * HW;
    const int b = blockIdx.z;
    const int k = blockIdx.y * 8 + (threadIdx.x >> 5);
    const int p = blockIdx.x * 32 + (threadIdx.x & 31);
    if (k >= K2 || p >= HW) return;

    const int D  = 2 * disp + 1;
    const int oy = (k / D - disp) * stride;
    const int ox = (k % D - disp) * stride;
    const int h = p / W, w = p % W;
    const int yy = h + oy, xx = w + ox;

    float out = 0.f;
    if (yy >= 0 && yy < H && xx >= 0 && xx < W) {
        const float* f1 = x + (size_t)(2 + b) * CHW + p;        // x[1][b]
        const float* f2 = x + (size_t)b * CHW + yy * W + xx;    // x[0][b] shifted
        float acc = 0.f;
#pragma unroll 8
        for (int c = 0; c < C_; c++)
            acc = fmaf(f1[(size_t)c * HW], f2[(size_t)c * HW], acc);
        out = acc * (1.f / C_);
    }
    g_corr[((size_t)(b * K2 + k)) * HW + p] = out;
}

// ---------------- 2. offset = w_off[72,K2] @ corr[K2,HW] ----------------
__global__ void offset_kernel(const float* __restrict__ w_off, int HW, int K2)
{
    const int b = blockIdx.z;
    const int o = blockIdx.y * 8 + (threadIdx.x >> 5);
    const int p = blockIdx.x * 32 + (threadIdx.x & 31);
    if (o >= 72 || p >= HW) return;

    const float* cb   = g_corr + (size_t)b * K2 * HW + p;
    const float* wrow = w_off + o * K2;
    float acc = 0.f;
#pragma unroll 4
    for (int k = 0; k < K2; k++)
        acc = fmaf(wrow[k], cb[(size_t)k * HW], acc);
    g_off[((size_t)(b * 72 + o)) * HW + p] = acc;
}

// ---------------- 3. bilinear im2col for deform conv ----------------
// col[n, c*9+k, p] = bilinear(x[1][n] channel c, coords from offsets)
__global__ void im2col_kernel(const float* __restrict__ x, int H, int W)
{
    const int HW = H * W;
    const size_t total = (size_t)B_ * C_ * 9 * HW;
    size_t idx = (size_t)blockIdx.x * blockDim.x + threadIdx.x;
    if (idx >= total) return;

    const int p = (int)(idx % HW);
    size_t r = idx / HW;
    const int k = (int)(r % 9); r /= 9;
    const int c = (int)(r % C_);
    const int n = (int)(r / C_);
    const int g = c >> 6;                        // channel group (cg=64)
    const int h = p / W, w = p % W;

    const float* ob = g_off + ((size_t)(n * 72 + (g * 9 + k) * 2)) * HW + p;
    const float oy = ob[0];
    const float ox = ob[HW];

    const float y  = (float)(k / 3 - 1 + h) + oy;
    const float xf = (float)(k % 3 - 1 + w) + ox;
    const float y0f = floorf(y), x0f = floorf(xf);
    const float wy = y - y0f, wx = xf - x0f;
    const int y0 = (int)y0f, x0 = (int)x0f;

    const float* img = x + ((size_t)(2 + n) * C_ + c) * HW;  // x[1][n], chan c
    const bool yv0 = (y0 >= 0)     & (y0 < H);
    const bool yv1 = (y0 + 1 >= 0) & (y0 + 1 < H);
    const bool xv0 = (x0 >= 0)     & (x0 < W);
    const bool xv1 = (x0 + 1 >= 0) & (x0 + 1 < W);
    const float v00 = (yv0 && xv0) ? img[(size_t)y0 * W + x0]           : 0.f;
    const float v01 = (yv0 && xv1) ? img[(size_t)y0 * W + x0 + 1]       : 0.f;
    const float v10 = (yv1 && xv0) ? img[(size_t)(y0 + 1) * W + x0]     : 0.f;
    const float v11 = (yv1 && xv1) ? img[(size_t)(y0 + 1) * W + x0 + 1] : 0.f;

    const float val = v00 * (1.f - wy) * (1.f - wx) + v01 * (1.f - wy) * wx
                    + v10 * wy * (1.f - wx)         + v11 * wy * wx;

    g_col[((size_t)n * KCOL + (size_t)(c * 9 + k)) * HW + p] = val;
}

// ---------------- 4. GEMM [256 x 2304] @ [2304 x HW] + ReLU ----------------
// BM=128, BN=64, BK=16, 256 threads, 8x4 register tile,
// global->register prefetch double buffering.
__global__ void __launch_bounds__(256)
gemm_relu_kernel(const float* __restrict__ A,  // w_adapt [256,2304]
                 float* __restrict__ out_base, // level output base
                 int N)                        // HW
{
    const int n_idx = blockIdx.z;
    const float* __restrict__ Bm = g_col + (size_t)n_idx * KCOL * N;
    float* __restrict__ Cm = out_base + ((size_t)(2 + n_idx)) * C_ * N;

    const int bm = blockIdx.y * 128;
    const int bn = blockIdx.x * 64;

    __shared__ float As[16][129];   // transposed A tile, padded
    __shared__ float Bs[16][64];

    const int tid = threadIdx.x;
    const int tx = tid & 15;        // 16 col-groups of 4  -> n
    const int ty = tid >> 4;        // 16 row-groups of 8  -> m

    // A loader: thread -> row ar (0..127), k-offset ac in {0, 8}
    const int ar = tid >> 1;
    const int ac = (tid & 1) * 8;
    // B loader: row br (0..15), col bc (float4)
    const int br = tid >> 4;
    const int bc = (tid & 15) * 4;

    const float* aPtr = A  + (size_t)(bm + ar) * KCOL + ac;
    const float* bPtr = Bm + (size_t)br * N + bn + bc;

    float acc[8][4] = {};

    // prologue prefetch (k0 = 0)
    float4 pa0 = *(const float4*)(aPtr);
    float4 pa1 = *(const float4*)(aPtr + 4);
    float4 pb  = *(const float4*)(bPtr);

    for (int k0 = 0; k0 < KCOL; k0 += 16) {
        // commit prefetched tile to smem
        As[ac + 0][ar] = pa0.x; As[ac + 1][ar] = pa0.y;
        As[ac + 2][ar] = pa0.z; As[ac + 3][ar] = pa0.w;
        As[ac + 4][ar] = pa1.x; As[ac + 5][ar] = pa1.y;
        As[ac + 6][ar] = pa1.z; As[ac + 7][ar] = pa1.w;
        *(float4*)&Bs[br][bc] = pb;
        __syncthreads();

        // prefetch next tile (hidden behind compute below)
        if (k0 + 16 < KCOL) {
            pa0 = *(const float4*)(aPtr + k0 + 16);
            pa1 = *(const float4*)(aPtr + k0 + 20);
            pb  = *(const float4*)(bPtr + (size_t)(k0 + 16) * N);
        }

#pragma unroll
        for (int kk = 0; kk < 16; kk++) {
            float a[8], b[4];
#pragma unroll
            for (int i = 0; i < 8; i++) a[i] = As[kk][ty * 8 + i];
#pragma unroll
            for (int j = 0; j < 4; j++) b[j] = Bs[kk][tx * 4 + j];
#pragma unroll
            for (int i = 0; i < 8; i++)
#pragma unroll
                for (int j = 0; j < 4; j++)
                    acc[i][j] = fmaf(a[i], b[j], acc[i][j]);
        }
        __syncthreads();
    }

#pragma unroll
    for (int i = 0; i < 8; i++) {
        const int m = bm + ty * 8 + i;
        float4 v;
        v.x = fmaxf(acc[i][0], 0.f);
        v.y = fmaxf(acc[i][1], 0.f);
        v.z = fmaxf(acc[i][2], 0.f);
        v.w = fmaxf(acc[i][3], 0.f);
        *(float4*)&Cm[(size_t)m * N + bn + tx * 4] = v;
    }
}

// ---------------- host orchestration ----------------
extern "C" void kernel_launch(void* const* d_in, const int* in_sizes, int n_in,
                              void* d_out, int out_size)
{
    static const int Hs[4]      = {64, 32, 16, 8};
    static const int disps[4]   = {8, 8, 4, 2};
    static const int strides[4] = {2, 1, 1, 1};

    // Input layout detection. setup_inputs() inserts weights INTERLEAVED:
    //   x0..x3, w_off0, w_adapt0, w_off1, w_adapt1, ...
    // but guard against a grouped layout (w_off0..3, w_adapt0..3) too.
    // w_adapt is always 256*256*9 = 589824 elems; w_off is <= 20808.
    const bool interleaved = (n_in >= 6) && (in_sizes[5] > 100000);

    float* out = (float*)d_out;
    size_t out_off = 0;

    for (int l = 0; l < 4; l++) {
        const int H = Hs[l], W = H, HW = H * W;
        const int disp = disps[l], stride = strides[l];
        const int D = 2 * disp + 1;
        const int K2 = D * D;
        const float* x       = (const float*)d_in[l];
        const float* w_off   = (const float*)d_in[interleaved ? (4 + 2 * l) : (4 + l)];
        const float* w_adapt = (const float*)d_in[interleaved ? (5 + 2 * l) : (8 + l)];
        const size_t CHW = (size_t)C_ * HW;

        // passthrough: out[0:2] = x[0]
        cudaMemcpyAsync(out + out_off, x, (size_t)B_ * CHW * sizeof(float),
                        cudaMemcpyDeviceToDevice);

        dim3 cgrid((HW + 31) / 32, (K2 + 7) / 8, B_);
        corr_kernel<<<cgrid, 256>>>(x, H, W, disp, stride, K2);

        dim3 ogrid((HW + 31) / 32, 9, B_);
        offset_kernel<<<ogrid, 256>>>(w_off, HW, K2);

        const size_t total = (size_t)B_ * C_ * 9 * HW;
        im2col_kernel<<<(unsigned)((total + 255) / 256), 256>>>(x, H, W);

        dim3 ggrid(HW / 64, C_ / 128, B_);
        gemm_relu_kernel<<<ggrid, 256>>>(w_adapt, out + out_off, HW);

        out_off += (size_t)4 * CHW;   // [x0 (2 batches), feat (2 batches)] * C * HW
    }
}